// round 14
// baseline (speedup 1.0000x reference)
#include <cuda_runtime.h>
#include <cuda_fp16.h>
#include <cstdint>

// ---------------- problem constants ----------------
#define T_STEPS 256
#define BATCH   64
#define HID     4096
#define G4      16384
#define NINP    64
#define KC      64            // K elements per chunk
#define CHUNKS  65            // 64 hidden chunks + 1 input chunk
#define TILES   256           // CTAs; 16 hidden units per CTA
#define NSTAGE  5             // 65 % 5 == 0 -> clean slot cycling across steps
#define A_U32   2048          // x chunk: 64 b x 64 k fp16 A-fragments = 8KB
#define B_U32   2048          // W chunk per tile: 64 rows x 64 k fp16 B-fragments = 8KB
#define A_BYTES 8192
#define B_BYTES 8192
#define STAGE_BYTES (A_BYTES + B_BYTES)
#define GSM_OFF  (NSTAGE*STAGE_BYTES)         // 81920
#define SMEM_DYN (GSM_OFF + 64*68*4)          // + 17408 = 99328 -> 2 CTAs/SM

// ---------------- device scratch ----------------
__device__ uint32_t g_wpack[(size_t)TILES * CHUNKS * B_U32];  // 136MB fp16 B-fragments
__device__ float    g_bsum[G4];
__device__ uint32_t g_embpack[(size_t)T_STEPS * A_U32];       // fp16 A-fragments per t
__device__ uint32_t g_xpack[2][KC * A_U32];                   // h double buffer
__device__ float    g_c[BATCH * HID];
__device__ unsigned g_bcount;
__device__ volatile unsigned g_bgen;

// ---------------- helpers ----------------
#define DI __device__ __forceinline__

DI uint32_t smem_u32(const void* p) {
    uint32_t a;
    asm("{ .reg .u64 t; cvta.to.shared.u64 t, %1; cvt.u32.u64 %0, t; }" : "=r"(a) : "l"(p));
    return a;
}
DI void cpasync16(uint32_t dst, const void* src) {
    asm volatile("cp.async.cg.shared.global [%0], [%1], 16;" :: "r"(dst), "l"(src) : "memory");
}
DI void cp_commit() { asm volatile("cp.async.commit_group;" ::: "memory"); }
template <int N> DI void cp_wait() { asm volatile("cp.async.wait_group %0;" :: "n"(N) : "memory"); }

// m16n8k16 fp16 MMA, fp32 accum
DI void mma_f16(float* d, const uint32_t* a, const uint32_t* b) {
    asm volatile(
        "mma.sync.aligned.m16n8k16.row.col.f32.f16.f16.f32 "
        "{%0,%1,%2,%3}, {%4,%5,%6,%7}, {%8,%9}, {%0,%1,%2,%3};"
        : "+f"(d[0]), "+f"(d[1]), "+f"(d[2]), "+f"(d[3])
        : "r"(a[0]), "r"(a[1]), "r"(a[2]), "r"(a[3]), "r"(b[0]), "r"(b[1]));
}
DI float sigm(float x) { return 1.0f / (1.0f + __expf(-x)); }
DI uint32_t pack_h2(float lo, float hi) {
    return (uint32_t)__half_as_ushort(__float2half_rn(lo)) |
           ((uint32_t)__half_as_ushort(__float2half_rn(hi)) << 16);
}

// ---------------- pack kernel ----------------
// B-fragment per (tile,kc): 2048 u32 = [ks(4)][wr(2)][np(2)][lane(32)][q(4)]
// nt = np*2 + (q>>1), reg = q&1
// k = ks*16 + (lane&3)*2 + reg*8 + {0,1}
// row n = wr*32 + nt*8 + (lane>>2); gate g = n>>4; hid = tile*16 + (n&15)
__global__ void pack_kernel(const float* __restrict__ w_ih, const float* __restrict__ w_hh) {
    int blk  = blockIdx.x;             // tile*CHUNKS + kc
    int tile = blk / CHUNKS;
    int kc   = blk % CHUNKS;
    uint32_t* dst = g_wpack + (size_t)blk * B_U32;
    #pragma unroll
    for (int j = 0; j < 8; j++) {
        int v    = threadIdx.x + j * 256;
        int q    = v & 3;
        int lane = (v >> 2) & 31;
        int np   = (v >> 7) & 1;
        int wr   = (v >> 8) & 1;
        int ks   = v >> 9;
        int nt   = np * 2 + (q >> 1);
        int reg  = q & 1;
        int k    = ks * 16 + (lane & 3) * 2 + reg * 8;
        int n    = wr * 32 + nt * 8 + (lane >> 2);
        int g    = n >> 4;
        int hid  = tile * 16 + (n & 15);
        size_t srow = (size_t)g * HID + hid;
        float2 val;
        if (kc < 64) val = *(const float2*)&w_hh[srow * HID + (size_t)kc * KC + k];
        else         val = *(const float2*)&w_ih[srow * NINP + k];
        dst[v] = pack_h2(val.x, val.y);
    }
}

// ---------------- init: bias sum, emb A-fragment pack, zero x0/c0, barrier reset ----------------
// A-fragment per chunk: 2048 u32 = [ks(4)][mt(4)][lane(32)][reg(4)]
// b = mt*16 + (lane>>2) + (reg&1)*8 ; k = ks*16 + (lane&3)*2 + (reg>>1)*8 + {0,1}
__global__ void init_kernel(const int* __restrict__ tokens,
                            const float* __restrict__ emb_table,
                            const float* __restrict__ b_ih,
                            const float* __restrict__ b_hh) {
    int i = blockIdx.x * blockDim.x + threadIdx.x;
    if (i == 0) { g_bcount = 0; g_bgen = 0; }
    if (i < T_STEPS * A_U32) {
        int t = i >> 11;
        int v = i & 2047;
        int reg = v & 3, lane = (v >> 2) & 31, mt = (v >> 7) & 3, ks = v >> 9;
        int b = mt * 16 + (lane >> 2) + (reg & 1) * 8;
        int k = ks * 16 + (lane & 3) * 2 + (reg >> 1) * 8;
        int tok = tokens[t * BATCH + b];
        float2 e = *(const float2*)&emb_table[tok * NINP + k];
        g_embpack[i] = pack_h2(e.x, e.y);
    }
    if (i < KC * A_U32)     g_xpack[0][i] = 0u;
    if (i < BATCH * HID)    g_c[i] = 0.0f;
    if (i < G4)             g_bsum[i] = b_ih[i] + b_hh[i];
}

// ---------------- persistent recurrent kernel ----------------
// 256 CTAs x 128 threads, 2 CTAs/SM, all co-resident (256 <= 296). One kernel runs
// all 256 steps with a grid spin-barrier between steps. Weights (B) for the next
// step's first 4 chunks are prefetched BEFORE the barrier (weights don't depend on h);
// only the A-halves are issued after it -> continuous DRAM stream across steps.
// Cross-CTA h (g_xpack) is read exclusively via cp.async.cg (L1-bypassing).
__global__ void __launch_bounds__(128, 2)
lstm_kernel(const int* __restrict__ seq_len, float* __restrict__ out) {
    extern __shared__ char smem_al[];
    const int tid  = threadIdx.x;
    const int warp = tid >> 5;
    const int lane = tid & 31;
    const int tile = blockIdx.x;
    const int wr   = warp & 1;           // row half (32 rows)
    const int wb   = warp >> 1;          // batch half (32 batch)

    uint32_t sb = smem_u32(smem_al);
    const uint32_t* wB = g_wpack + (size_t)tile * (CHUNKS * B_U32);

    // zigzag mapping for step tt
    auto phys = [&](int tt, int l) { return (tt & 1) ? (CHUNKS - 1 - l) : l; };

    auto issueA = [&](int tt, int kc, int s) {
        const uint32_t* xsrc = (kc < 64) ? (g_xpack[tt & 1] + (size_t)kc * A_U32)
                                         : (g_embpack + (size_t)tt * A_U32);
        uint32_t ab = sb + (uint32_t)s * STAGE_BYTES;
        #pragma unroll
        for (int i = 0; i < 4; i++) {
            int u = i * 128 + tid;
            cpasync16(ab + (uint32_t)u * 16, (const char*)xsrc + (size_t)u * 16);
        }
    };
    auto issueB = [&](int kc, int s) {
        uint32_t bb = sb + (uint32_t)s * STAGE_BYTES + A_BYTES;
        const char* bsrc = (const char*)(wB + (size_t)kc * B_U32);
        #pragma unroll
        for (int i = 0; i < 4; i++) {
            int u = i * 128 + tid;
            cpasync16(bb + (uint32_t)u * 16, bsrc + (size_t)u * 16);
        }
    };

    // prologue for t=0: B groups then A groups for chunks 0..3
    #pragma unroll
    for (int s = 0; s < NSTAGE - 1; s++) { issueB(phys(0, s), s); cp_commit(); }
    #pragma unroll
    for (int s = 0; s < NSTAGE - 1; s++) { issueA(0, phys(0, s), s); cp_commit(); }

    float* gsm = (float*)(smem_al + GSM_OFF);
    uint32_t* xn;
    const int hidbase = tile * 16;

    for (int t = 0; t < T_STEPS; ++t) {
        float acc[2][4][4];
        #pragma unroll
        for (int mt = 0; mt < 2; mt++)
            #pragma unroll
            for (int nt = 0; nt < 4; nt++)
                #pragma unroll
                for (int c = 0; c < 4; c++) acc[mt][nt][c] = 0.0f;

        for (int k = 0; k < CHUNKS; ++k) {
            cp_wait<3>();
            __syncthreads();
            int pre = k + NSTAGE - 1;
            if (pre < CHUNKS) {
                int kc = phys(t, pre);
                issueA(t, kc, pre % NSTAGE);
                issueB(kc, pre % NSTAGE);
            } else if (t + 1 < T_STEPS) {
                int c = pre - CHUNKS;                    // next step chunk 0..3
                issueB(phys(t + 1, c), c % NSTAGE);      // weights only; h not ready
            }
            cp_commit();

            int s = k % NSTAGE;
            const char* sA = smem_al + (size_t)s * STAGE_BYTES;
            const char* sB = sA + A_BYTES;
            #pragma unroll
            for (int ks = 0; ks < 4; ks++) {
                uint32_t af[2][4];
                #pragma unroll
                for (int mt = 0; mt < 2; mt++) {
                    uint4 vv = *(const uint4*)(sA + ks * 2048 + (wb * 2 + mt) * 512 + lane * 16);
                    af[mt][0] = vv.x; af[mt][1] = vv.y; af[mt][2] = vv.z; af[mt][3] = vv.w;
                }
                uint32_t bf[4][2];
                #pragma unroll
                for (int np = 0; np < 2; np++) {
                    uint4 vv = *(const uint4*)(sB + ((ks * 2 + wr) * 2 + np) * 512 + lane * 16);
                    bf[2 * np][0] = vv.x;     bf[2 * np][1] = vv.y;
                    bf[2 * np + 1][0] = vv.z; bf[2 * np + 1][1] = vv.w;
                }
                #pragma unroll
                for (int mt = 0; mt < 2; mt++)
                    #pragma unroll
                    for (int nt = 0; nt < 4; nt++)
                        mma_f16(acc[mt][nt], af[mt], bf[nt]);
            }
        }

        // ---- epilogue: C fragments -> gsm [batch 64][rows 64] stride 68 (own region) ----
        #pragma unroll
        for (int mt = 0; mt < 2; mt++)
            #pragma unroll
            for (int nt = 0; nt < 4; nt++) {
                int b0 = (wb * 2 + mt) * 16 + (lane >> 2);
                int n  = wr * 32 + nt * 8 + 2 * (lane & 3);
                *(float2*)&gsm[b0 * 68 + n]       = make_float2(acc[mt][nt][0], acc[mt][nt][1]);
                *(float2*)&gsm[(b0 + 8) * 68 + n] = make_float2(acc[mt][nt][2], acc[mt][nt][3]);
            }
        __syncthreads();

        // LSTM update; write h as fp16 pairs directly in A-fragment order.
        xn = g_xpack[(t + 1) & 1];
        #pragma unroll
        for (int i = 0; i < 4; i++) {
            int u  = i * 128 + tid;
            int hp = u & 7;
            int b  = u >> 3;
            int h0 = hp * 2, h1 = hp * 2 + 1;
            float gi0 = gsm[b * 68 +  0 + h0] + g_bsum[0 * HID + hidbase + h0];
            float gf0 = gsm[b * 68 + 16 + h0] + g_bsum[1 * HID + hidbase + h0];
            float gg0 = gsm[b * 68 + 32 + h0] + g_bsum[2 * HID + hidbase + h0];
            float go0 = gsm[b * 68 + 48 + h0] + g_bsum[3 * HID + hidbase + h0];
            float gi1 = gsm[b * 68 +  0 + h1] + g_bsum[0 * HID + hidbase + h1];
            float gf1 = gsm[b * 68 + 16 + h1] + g_bsum[1 * HID + hidbase + h1];
            float gg1 = gsm[b * 68 + 32 + h1] + g_bsum[2 * HID + hidbase + h1];
            float go1 = gsm[b * 68 + 48 + h1] + g_bsum[3 * HID + hidbase + h1];
            int idx0 = b * HID + hidbase + h0;
            int idx1 = idx0 + 1;
            float c0 = sigm(gf0) * g_c[idx0] + sigm(gi0) * tanhf(gg0);
            float c1 = sigm(gf1) * g_c[idx1] + sigm(gi1) * tanhf(gg1);
            g_c[idx0] = c0; g_c[idx1] = c1;
            float hh0 = sigm(go0) * tanhf(c0);
            float hh1 = sigm(go1) * tanhf(c1);
            int ksx  = tile & 3;
            int lnx  = ((b & 7) << 2) | (hp & 3);
            int regx = ((hp >> 2) << 1) | ((b >> 3) & 1);
            int mtx  = b >> 4;
            xn[(tile >> 2) * A_U32 + ((ksx * 4 + mtx) * 32 + lnx) * 4 + regx] = pack_h2(hh0, hh1);
            if (t == __ldg(&seq_len[b]) - 1) { out[idx0] = c0; out[idx1] = c1; }
        }

        if (t + 1 < T_STEPS) {
            // grid barrier (sense-reversing, monotonic gen)
            __threadfence();
            __syncthreads();
            if (tid == 0) {
                unsigned gen = g_bgen;
                if (atomicAdd(&g_bcount, 1) == TILES - 1) {
                    g_bcount = 0;
                    __threadfence();
                    g_bgen = gen + 1;
                } else {
                    while (g_bgen == gen) __nanosleep(64);
                }
            }
            __syncthreads();
            // A-halves for next step's chunks 0..3 (B already in flight)
            #pragma unroll
            for (int c = 0; c < NSTAGE - 1; c++) {
                issueA(t + 1, phys(t + 1, c), c % NSTAGE);
                cp_commit();
            }
        }
    }
}

// ---------------- launch ----------------
extern "C" void kernel_launch(void* const* d_in, const int* in_sizes, int n_in,
                              void* d_out, int out_size) {
    const int*   tokens    = (const int*)d_in[0];
    const int*   seq_len   = (const int*)d_in[1];
    const float* emb_table = (const float*)d_in[2];
    const float* w_ih      = (const float*)d_in[3];
    const float* w_hh      = (const float*)d_in[4];
    const float* b_ih      = (const float*)d_in[5];
    const float* b_hh      = (const float*)d_in[6];
    float* out = (float*)d_out;

    cudaFuncSetAttribute(lstm_kernel, cudaFuncAttributeMaxDynamicSharedMemorySize, SMEM_DYN);

    pack_kernel<<<TILES * CHUNKS, 256>>>(w_ih, w_hh);
    init_kernel<<<(T_STEPS * A_U32 + 255) / 256, 256>>>(tokens, emb_table, b_ih, b_hh);
    lstm_kernel<<<TILES, 128, SMEM_DYN>>>(seq_len, out);
}

// round 15
// speedup vs baseline: 1.0540x; 1.0540x over previous
#include <cuda_runtime.h>
#include <cuda_fp16.h>
#include <cstdint>

// ---------------- problem constants ----------------
#define T_STEPS 256
#define BATCH   64
#define HID     4096
#define G4      16384
#define NINP    64
#define KC      64            // K elements per chunk
#define CHUNKS  65            // 64 hidden chunks + 1 input chunk
#define TILES   256           // CTAs; 16 hidden units per CTA
#define NSTAGE  6
#define PDIST   4             // prefetch distance (chunks ahead)
#define A_U32   2048          // x chunk: 64 b x 64 k fp16 A-fragments = 8KB
#define B_U32   2048          // W chunk per tile: 64 rows x 64 k fp16 B-fragments = 8KB
#define A_BYTES 8192
#define B_BYTES 8192
#define STAGE_BYTES (A_BYTES + B_BYTES)
#define SMEM_DYN (NSTAGE*STAGE_BYTES)   // 96KB -> 2 CTAs/SM

// ---------------- device scratch ----------------
__device__ uint32_t g_wpack[(size_t)TILES * CHUNKS * B_U32];  // 136MB fp16 B-fragments
__device__ float    g_bsum[G4];
__device__ uint32_t g_embpack[(size_t)T_STEPS * A_U32];       // fp16 A-fragments per t
__device__ uint32_t g_xpack[2][KC * A_U32];                   // h double buffer
__device__ float    g_c[BATCH * HID];

// ---------------- helpers ----------------
#define DI __device__ __forceinline__

DI uint32_t smem_u32(const void* p) {
    uint32_t a;
    asm("{ .reg .u64 t; cvta.to.shared.u64 t, %1; cvt.u32.u64 %0, t; }" : "=r"(a) : "l"(p));
    return a;
}
DI void cpasync16(uint32_t dst, const void* src) {
    asm volatile("cp.async.cg.shared.global [%0], [%1], 16;" :: "r"(dst), "l"(src) : "memory");
}
DI void cp_commit() { asm volatile("cp.async.commit_group;" ::: "memory"); }
template <int N> DI void cp_wait() { asm volatile("cp.async.wait_group %0;" :: "n"(N) : "memory"); }

// m16n8k16 fp16 MMA, fp32 accum
DI void mma_f16(float* d, const uint32_t* a, const uint32_t* b) {
    asm volatile(
        "mma.sync.aligned.m16n8k16.row.col.f32.f16.f16.f32 "
        "{%0,%1,%2,%3}, {%4,%5,%6,%7}, {%8,%9}, {%0,%1,%2,%3};"
        : "+f"(d[0]), "+f"(d[1]), "+f"(d[2]), "+f"(d[3])
        : "r"(a[0]), "r"(a[1]), "r"(a[2]), "r"(a[3]), "r"(b[0]), "r"(b[1]));
}
DI float sigm(float x) { return 1.0f / (1.0f + __expf(-x)); }
DI uint32_t pack_h2(float lo, float hi) {
    return (uint32_t)__half_as_ushort(__float2half_rn(lo)) |
           ((uint32_t)__half_as_ushort(__float2half_rn(hi)) << 16);
}

// ---------------- pack kernel ----------------
// B-fragment per (tile,kc): 2048 u32 = [ks(4)][wr(2)][np(2)][lane(32)][q(4)]
// nt = np*2 + (q>>1), reg = q&1
// k = ks*16 + (lane&3)*2 + reg*8 + {0,1}
// row n = wr*32 + nt*8 + (lane>>2); gate g = n>>4; hid = tile*16 + (n&15)
__global__ void pack_kernel(const float* __restrict__ w_ih, const float* __restrict__ w_hh) {
    int blk  = blockIdx.x;             // tile*CHUNKS + kc
    int tile = blk / CHUNKS;
    int kc   = blk % CHUNKS;
    uint32_t* dst = g_wpack + (size_t)blk * B_U32;
    #pragma unroll
    for (int j = 0; j < 8; j++) {
        int v    = threadIdx.x + j * 256;
        int q    = v & 3;
        int lane = (v >> 2) & 31;
        int np   = (v >> 7) & 1;
        int wr   = (v >> 8) & 1;
        int ks   = v >> 9;
        int nt   = np * 2 + (q >> 1);
        int reg  = q & 1;
        int k    = ks * 16 + (lane & 3) * 2 + reg * 8;
        int n    = wr * 32 + nt * 8 + (lane >> 2);
        int g    = n >> 4;
        int hid  = tile * 16 + (n & 15);
        size_t srow = (size_t)g * HID + hid;
        float2 val;
        if (kc < 64) val = *(const float2*)&w_hh[srow * HID + (size_t)kc * KC + k];
        else         val = *(const float2*)&w_ih[srow * NINP + k];
        dst[v] = pack_h2(val.x, val.y);
    }
}

// ---------------- init: bias sum, emb A-fragment pack, zero x0/c0 ----------------
// A-fragment per chunk: 2048 u32 = [ks(4)][mt(4)][lane(32)][reg(4)]
// b = mt*16 + (lane>>2) + (reg&1)*8 ; k = ks*16 + (lane&3)*2 + (reg>>1)*8 + {0,1}
__global__ void init_kernel(const int* __restrict__ tokens,
                            const float* __restrict__ emb_table,
                            const float* __restrict__ b_ih,
                            const float* __restrict__ b_hh) {
    int i = blockIdx.x * blockDim.x + threadIdx.x;
    if (i < T_STEPS * A_U32) {
        int t = i >> 11;
        int v = i & 2047;
        int reg = v & 3, lane = (v >> 2) & 31, mt = (v >> 7) & 3, ks = v >> 9;
        int b = mt * 16 + (lane >> 2) + (reg & 1) * 8;
        int k = ks * 16 + (lane & 3) * 2 + (reg >> 1) * 8;
        int tok = tokens[t * BATCH + b];
        float2 e = *(const float2*)&emb_table[tok * NINP + k];
        g_embpack[i] = pack_h2(e.x, e.y);
    }
    if (i < KC * A_U32)     g_xpack[0][i] = 0u;
    if (i < BATCH * HID)    g_c[i] = 0.0f;
    if (i < G4)             g_bsum[i] = b_ih[i] + b_hh[i];
}

// ---------------- one recurrent step ----------------
// 256 CTAs x 128 threads (4 warps), 2 CTAs/SM. CTA: 16 hidden units, M=64 gate rows.
// Prefetch distance 4 on a 6-slot ring; wait<2> + barrier only on EVEN chunks:
//  - visibility: wait<2> at even k completes chunks <= k+1 per-thread (in-order groups);
//    barrier publishes the pair to all warps. Odd iter reads published data only.
//  - WAR: even-k issue hits slot (k-2)%6 (consumed iter k-2), odd-k issue slot (k-1)%6;
//    both covered by the barrier at iter k.
__global__ void __launch_bounds__(128, 2)
step_kernel(int t, const int* __restrict__ seq_len, float* __restrict__ out) {
    extern __shared__ char smem_al[];
    const int tid  = threadIdx.x;
    const int warp = tid >> 5;
    const int lane = tid & 31;
    const int tile = blockIdx.x;
    const int wr   = warp & 1;           // row half (32 rows)
    const int wb   = warp >> 1;          // batch half (32 batch)
    const int rev  = t & 1;              // zigzag direction

    uint32_t sb = smem_u32(smem_al);

    const uint32_t* wB   = g_wpack + (size_t)tile * (CHUNKS * B_U32);
    const uint32_t* xcur = g_xpack[t & 1];
    const uint32_t* embt = g_embpack + (size_t)t * A_U32;

    auto phys = [&](int l) { return rev ? (CHUNKS - 1 - l) : l; };

    auto load_stage = [&](int l, int s) {
        int kc = phys(l);
        uint32_t ab = sb + (uint32_t)s * STAGE_BYTES;
        const char* asrc = (kc < 64) ? (const char*)(xcur + (size_t)kc * A_U32)
                                     : (const char*)embt;
        #pragma unroll
        for (int i = 0; i < 4; i++) {                 // A: 8KB linear
            int u = i * 128 + tid;
            cpasync16(ab + (uint32_t)u * 16, asrc + (size_t)u * 16);
        }
        uint32_t bb = ab + A_BYTES;
        const char* bsrc = (const char*)(wB + (size_t)kc * B_U32);
        #pragma unroll
        for (int i = 0; i < 4; i++) {                 // B: 8KB linear
            int u = i * 128 + tid;
            cpasync16(bb + (uint32_t)u * 16, bsrc + (size_t)u * 16);
        }
    };

    // prologue: chunks 0..3 into slots 0..3
    #pragma unroll
    for (int s = 0; s < PDIST; s++) { load_stage(s, s); cp_commit(); }

    float acc[2][4][4];                               // [mt][nt][c]
    #pragma unroll
    for (int mt = 0; mt < 2; mt++)
        #pragma unroll
        for (int nt = 0; nt < 4; nt++)
            #pragma unroll
            for (int c = 0; c < 4; c++) acc[mt][nt][c] = 0.0f;

    for (int k = 0; k < CHUNKS; ++k) {
        if ((k & 1) == 0) {
            cp_wait<2>();                 // chunks <= k+1 complete (per thread, in order)
            __syncthreads();              // publish pair; free slots (k-2),(k-1)
        }
        if (k + PDIST < CHUNKS) load_stage(k + PDIST, (k + PDIST) % NSTAGE);
        cp_commit();                      // one group per iteration (empty at tail)

        int s = k % NSTAGE;
        const char* sA = smem_al + (size_t)s * STAGE_BYTES;
        const char* sB = sA + A_BYTES;

        #pragma unroll
        for (int ks = 0; ks < 4; ks++) {
            uint32_t af[2][4];
            #pragma unroll
            for (int mt = 0; mt < 2; mt++) {
                uint4 vv = *(const uint4*)(sA + ks * 2048 + (wb * 2 + mt) * 512 + lane * 16);
                af[mt][0] = vv.x; af[mt][1] = vv.y; af[mt][2] = vv.z; af[mt][3] = vv.w;
            }
            uint32_t bf[4][2];
            #pragma unroll
            for (int np = 0; np < 2; np++) {
                uint4 vv = *(const uint4*)(sB + ((ks * 2 + wr) * 2 + np) * 512 + lane * 16);
                bf[2 * np][0] = vv.x;     bf[2 * np][1] = vv.y;
                bf[2 * np + 1][0] = vv.z; bf[2 * np + 1][1] = vv.w;
            }
            #pragma unroll
            for (int mt = 0; mt < 2; mt++)
                #pragma unroll
                for (int nt = 0; nt < 4; nt++)
                    mma_f16(acc[mt][nt], af[mt], bf[nt]);
        }
    }

    cp_wait<0>();
    __syncthreads();                                  // stages dead; gsm aliases them

    // ---- epilogue: C fragments -> gsm [batch 64][rows 64] stride 68 ----
    float* gsm = (float*)smem_al;
    #pragma unroll
    for (int mt = 0; mt < 2; mt++)
        #pragma unroll
        for (int nt = 0; nt < 4; nt++) {
            int b0 = (wb * 2 + mt) * 16 + (lane >> 2);
            int n  = wr * 32 + nt * 8 + 2 * (lane & 3);
            *(float2*)&gsm[b0 * 68 + n]       = make_float2(acc[mt][nt][0], acc[mt][nt][1]);
            *(float2*)&gsm[(b0 + 8) * 68 + n] = make_float2(acc[mt][nt][2], acc[mt][nt][3]);
        }
    __syncthreads();

    // LSTM update; write h as fp16 pairs directly in A-fragment order.
    const int hidbase = tile * 16;
    uint32_t* xn = g_xpack[(t + 1) & 1];
    #pragma unroll
    for (int i = 0; i < 4; i++) {
        int u  = i * 128 + tid;              // 512 units: (b, hid pair hp)
        int hp = u & 7;
        int b  = u >> 3;
        int h0 = hp * 2, h1 = hp * 2 + 1;
        float gi0 = gsm[b * 68 +  0 + h0] + g_bsum[0 * HID + hidbase + h0];
        float gf0 = gsm[b * 68 + 16 + h0] + g_bsum[1 * HID + hidbase + h0];
        float gg0 = gsm[b * 68 + 32 + h0] + g_bsum[2 * HID + hidbase + h0];
        float go0 = gsm[b * 68 + 48 + h0] + g_bsum[3 * HID + hidbase + h0];
        float gi1 = gsm[b * 68 +  0 + h1] + g_bsum[0 * HID + hidbase + h1];
        float gf1 = gsm[b * 68 + 16 + h1] + g_bsum[1 * HID + hidbase + h1];
        float gg1 = gsm[b * 68 + 32 + h1] + g_bsum[2 * HID + hidbase + h1];
        float go1 = gsm[b * 68 + 48 + h1] + g_bsum[3 * HID + hidbase + h1];
        int idx0 = b * HID + hidbase + h0;
        int idx1 = idx0 + 1;
        float c0 = sigm(gf0) * g_c[idx0] + sigm(gi0) * tanhf(gg0);
        float c1 = sigm(gf1) * g_c[idx1] + sigm(gi1) * tanhf(gg1);
        g_c[idx0] = c0; g_c[idx1] = c1;
        float hh0 = sigm(go0) * tanhf(c0);
        float hh1 = sigm(go1) * tanhf(c1);
        int ksx  = tile & 3;
        int lnx  = ((b & 7) << 2) | (hp & 3);
        int regx = ((hp >> 2) << 1) | ((b >> 3) & 1);
        int mtx  = b >> 4;
        xn[(tile >> 2) * A_U32 + ((ksx * 4 + mtx) * 32 + lnx) * 4 + regx] = pack_h2(hh0, hh1);
        if (t == __ldg(&seq_len[b]) - 1) { out[idx0] = c0; out[idx1] = c1; }
    }
}

// ---------------- launch ----------------
extern "C" void kernel_launch(void* const* d_in, const int* in_sizes, int n_in,
                              void* d_out, int out_size) {
    const int*   tokens    = (const int*)d_in[0];
    const int*   seq_len   = (const int*)d_in[1];
    const float* emb_table = (const float*)d_in[2];
    const float* w_ih      = (const float*)d_in[3];
    const float* w_hh      = (const float*)d_in[4];
    const float* b_ih      = (const float*)d_in[5];
    const float* b_hh      = (const float*)d_in[6];
    float* out = (float*)d_out;

    cudaFuncSetAttribute(step_kernel, cudaFuncAttributeMaxDynamicSharedMemorySize, SMEM_DYN);

    pack_kernel<<<TILES * CHUNKS, 256>>>(w_ih, w_hh);
    init_kernel<<<(T_STEPS * A_U32 + 255) / 256, 256>>>(tokens, emb_table, b_ih, b_hh);

    for (int t = 0; t < T_STEPS; ++t) {
        step_kernel<<<TILES, 128, SMEM_DYN>>>(t, seq_len, out);
    }
}